// round 11
// baseline (speedup 1.0000x reference)
#include <cuda_runtime.h>
#include <math.h>

// Problem constants
#define MDIM 4096
#define NDIM 8192
#define DDIM 64

#define NTHR 1024           // single CTA: minimal dispatch; one float4 store each

#define EPSV    1e-8f
#define LOGEPS  (-18.420680743952367f)   // log(1e-8)

// Global-skip bound: t2 = -0.5*sq/sigma^2 <= 0 always (sq is a squared
// distance), so val = (1/n) * sum exp(t1 + t2) <= exp(t1).
// If t1 <= T1_SKIP (= -46): val <= 1e-20 and
//   |log(EPS + val) - log(EPS)| <= val/EPS <= 1e-12   (below fp32 ulp),
// for ARBITRARY x_eval / x_base — the bound depends only on log_sigma.
#define T1_SKIP (-46.0f)

// ---------------------------------------------------------------------------
// Terminal floor-class kernel: grid = 1 x 1024.
//   1) LDG log_sigma first (longest-latency op, overlaps everything)
//   2) 1024 x STG.128 of log(EPS) — covers all 4096 outputs, no data deps
//   3) provable-underflow branch resolves; fast path exits.
// Fallback (t1 > -46 only; never for this problem's inputs): exact
// per-row KDE, 4 rows/thread, overwriting the preliminary stores after a
// CTA-scope barrier (exactly one writer per row).
// ---------------------------------------------------------------------------
__global__ __launch_bounds__(NTHR)
void kde_fused(const float* __restrict__ xe,
               const float* __restrict__ xb,
               const float* __restrict__ logsig,
               float* __restrict__ out) {
    // 1) issue the load immediately
    const float ls = __ldg(logsig);

    // 2) unconditional constant stores (independent of the load)
    const int gt = threadIdx.x;                        // 0..1023
    float4 v = make_float4(LOGEPS, LOGEPS, LOGEPS, LOGEPS);
    ((float4*)out)[gt] = v;

    // 3) provable-underflow exit:  t1 = -0.5*D*log(2*pi) - log_sigma
    const float t1 = -0.5f * (float)DDIM * 1.8378770664093453f - ls;
    if (t1 <= T1_SKIP) return;          // val <= 1e-20: stores are the answer.

    // ---------------- fallback: exact, never performance-critical ----------
    __syncthreads();    // order preliminary stores before overwrites

    const float inv_s2 = __expf(-2.0f * ls);

    for (int row = gt; row < MDIM; row += NTHR) {
        const float4* xe4 = (const float4*)(xe + (size_t)row * DDIM);
        float acc = 0.0f;
        for (int j = 0; j < NDIM; j++) {
            const float4* xb4 = (const float4*)(xb + (size_t)j * DDIM);
            float sq = 0.0f;
#pragma unroll 4
            for (int k = 0; k < DDIM / 4; k++) {
                float4 a = xe4[k];
                float4 b = xb4[k];
                float d0 = a.x - b.x;
                float d1 = a.y - b.y;
                float d2 = a.z - b.z;
                float d3 = a.w - b.w;
                sq = fmaf(d0, d0, sq);
                sq = fmaf(d1, d1, sq);
                sq = fmaf(d2, d2, sq);
                sq = fmaf(d3, d3, sq);
            }
            acc += expf(t1 - 0.5f * sq * inv_s2);
        }
        out[row] = logf(EPSV + acc * (1.0f / (float)NDIM));
    }
}

// ---------------------------------------------------------------------------
extern "C" void kernel_launch(void* const* d_in, const int* in_sizes, int n_in,
                              void* d_out, int out_size) {
    const float* xe = (const float*)d_in[0];   // x_eval [4096,64]
    const float* xb = (const float*)d_in[1];   // x_base [8192,64]
    const float* ls = (const float*)d_in[2];   // log_sigma [1]
    float* out = (float*)d_out;                // [4096]

    kde_fused<<<1, NTHR>>>(xe, xb, ls, out);
}

// round 12
// speedup vs baseline: 1.1049x; 1.1049x over previous
#include <cuda_runtime.h>
#include <math.h>

// Problem constants
#define MDIM 4096
#define NDIM 8192
#define DDIM 64

#define NBLK 8
#define NTHR 128            // 1024 threads total: one float4 store each

#define EPSV    1e-8f
#define LOGEPS  (-18.420680743952367f)   // log(1e-8)

// Global-skip bound: t2 = -0.5*sq/sigma^2 <= 0 always (sq is a squared
// distance), so val = (1/n) * sum exp(t1 + t2) <= exp(t1).
// If t1 <= T1_SKIP (= -46): val <= 1e-20 and
//   |log(EPS + val) - log(EPS)| <= val/EPS <= 1e-12   (below fp32 ulp),
// for ARBITRARY x_eval / x_base — the bound depends only on log_sigma.
#define T1_SKIP (-46.0f)

// ---------------------------------------------------------------------------
// Terminal floor-class kernel (best-measured shape: 8 x 128).
//   1) LDG log_sigma first (longest-latency op, overlaps everything)
//   2) 1024 x STG.128 of log(EPS) — covers all 4096 outputs, no data deps,
//      fanned out across 8 CTAs / SMs / L2 partitions
//   3) provable-underflow branch resolves; fast path exits.
// Fallback (t1 > -46 only; never for this problem's inputs): exact
// grid-stride per-row KDE overwriting the preliminary stores after a
// CTA-scope barrier (exactly one writer per row).
// ---------------------------------------------------------------------------
__global__ __launch_bounds__(NTHR)
void kde_fused(const float* __restrict__ xe,
               const float* __restrict__ xb,
               const float* __restrict__ logsig,
               float* __restrict__ out) {
    // 1) issue the load immediately
    const float ls = __ldg(logsig);

    // 2) unconditional constant stores (independent of the load)
    const int gt = blockIdx.x * NTHR + threadIdx.x;   // 0..1023
    float4 v = make_float4(LOGEPS, LOGEPS, LOGEPS, LOGEPS);
    ((float4*)out)[gt] = v;

    // 3) provable-underflow exit:  t1 = -0.5*D*log(2*pi) - log_sigma
    const float t1 = -0.5f * (float)DDIM * 1.8378770664093453f - ls;
    if (t1 <= T1_SKIP) return;          // val <= 1e-20: stores are the answer.

    // ---------------- fallback: exact, never performance-critical ----------
    __syncthreads();    // order preliminary stores before overwrites

    const float inv_s2 = __expf(-2.0f * ls);

    for (int row = gt; row < MDIM; row += NBLK * NTHR) {
        const float4* xe4 = (const float4*)(xe + (size_t)row * DDIM);
        float acc = 0.0f;
        for (int j = 0; j < NDIM; j++) {
            const float4* xb4 = (const float4*)(xb + (size_t)j * DDIM);
            float sq = 0.0f;
#pragma unroll 4
            for (int k = 0; k < DDIM / 4; k++) {
                float4 a = xe4[k];
                float4 b = xb4[k];
                float d0 = a.x - b.x;
                float d1 = a.y - b.y;
                float d2 = a.z - b.z;
                float d3 = a.w - b.w;
                sq = fmaf(d0, d0, sq);
                sq = fmaf(d1, d1, sq);
                sq = fmaf(d2, d2, sq);
                sq = fmaf(d3, d3, sq);
            }
            acc += expf(t1 - 0.5f * sq * inv_s2);
        }
        out[row] = logf(EPSV + acc * (1.0f / (float)NDIM));
    }
}

// ---------------------------------------------------------------------------
extern "C" void kernel_launch(void* const* d_in, const int* in_sizes, int n_in,
                              void* d_out, int out_size) {
    const float* xe = (const float*)d_in[0];   // x_eval [4096,64]
    const float* xb = (const float*)d_in[1];   // x_base [8192,64]
    const float* ls = (const float*)d_in[2];   // log_sigma [1]
    float* out = (float*)d_out;                // [4096]

    kde_fused<<<NBLK, NTHR>>>(xe, xb, ls, out);
}